// round 3
// baseline (speedup 1.0000x reference)
#include <cuda_runtime.h>
#include <cstdint>

// Problem shape (fixed by reference setup_inputs)
#define BB 8
#define NN 32768
#define DD 128
#define HH 64
#define CC 64
#define TOK (BB*NN)
#define NSEG (BB*CC)

#define TILE 128
#define TILES_PER_CTA 4
#define TOK_PER_CTA (TILE*TILES_PER_CTA)   // 512
#define NCTA (TOK/TOK_PER_CTA)             // 512 CTAs, 64 per batch

// Static scratch (no runtime allocation)
__device__ float g_denom[NSEG];   // per-(batch,cluster) sum of e

// ---------------------------------------------------------------------------
// K0: zero output (atomic target) + denominators
// ---------------------------------------------------------------------------
__global__ void init_kernel(float* __restrict__ out) {
    int i = blockIdx.x * blockDim.x + threadIdx.x;
    if (i < NSEG * DD) out[i] = 0.0f;
    if (i < NSEG) g_denom[i] = 0.0f;
}

__device__ __forceinline__ uint32_t f2tf32(float v) {
    uint32_t u;
    asm("cvt.rna.tf32.f32 %0, %1;" : "=r"(u) : "f"(v));
    return u;
}

// ---------------------------------------------------------------------------
// K1 (fused): per 128-token tile:
//   phase A: tf32 mma.sync MLP  -> e = exp(sigmoid(.)) into smem (+ sden)
//   phase B: warp-per-D-slice accumulation  sacc[c*128+ds+lane] += e * f
//            (feature rows re-read -> L2 hit; warp-disjoint slices -> no races)
// CTA accumulates 512 tokens into a private 64x128 smem accumulator, then
// flushes once with global atomics. Features cross DRAM exactly once.
//
// Dynamic smem layout (floats):
//   [0,8320)      swA   : W1 as tf32 bits, [k][h], pitch 65 (conflict-free)
//   [8320,16512)  sacc  : 64x128 accumulator
//   [16512,16640) se    : e per tile token
//   [16640,16768) scl   : cluster id per tile token
//   [16768,16832) sden  : per-cluster e sum
//   [16832,16896) sW2   ; [16896,16960) sb1
// ---------------------------------------------------------------------------
__global__ __launch_bounds__(128) void fused_kernel(
    const float* __restrict__ feat, const int* __restrict__ assign,
    const float* __restrict__ W1, const float* __restrict__ b1,
    const float* __restrict__ W2, const float* __restrict__ b2,
    float* __restrict__ out)
{
    extern __shared__ float smem[];
    uint32_t* swA = reinterpret_cast<uint32_t*>(smem);
    float* sacc = smem + 8320;
    float* se   = smem + 16512;
    int*   scl  = reinterpret_cast<int*>(smem + 16640);
    float* sden = smem + 16768;
    float* sW2  = smem + 16832;
    float* sb1  = smem + 16896;

    const int tid  = threadIdx.x;
    const int warp = tid >> 5, lane = tid & 31;
    const int g = lane >> 2, t = lane & 3;
    const int ds = warp * 32;                 // this warp's D-slice

    for (int i = tid; i < DD * HH; i += 128) {
        int k = i >> 6, h = i & 63;            // W1 row-major [128 k][64 h]
        swA[k * 65 + h] = f2tf32(W1[i]);
    }
    if (tid < HH) { sW2[tid] = W2[tid]; sb1[tid] = b1[tid]; }
    if (tid < CC) sden[tid] = 0.0f;
    for (int i = tid; i < CC * DD; i += 128) sacc[i] = 0.0f;
    __syncthreads();

    // Per-lane epilogue constants: lane's 8 hidden rows = 16*mt + 8*j + g
    float w2r[8], b1r[8];
    #pragma unroll
    for (int mt = 0; mt < 4; mt++)
        #pragma unroll
        for (int jj = 0; jj < 2; jj++) {
            int r = 16 * mt + 8 * jj + g;
            w2r[mt * 2 + jj] = sW2[r];
            b1r[mt * 2 + jj] = sb1[r];
        }

    const int ctaTokBase = blockIdx.x * TOK_PER_CTA;
    const int batch = ctaTokBase >> 15;        // 64 CTAs per batch
    const float b2v = __ldg(b2);

    for (int tile = 0; tile < TILES_PER_CTA; tile++) {
        const int tileBase = ctaTokBase + tile * TILE;
        const int tokBase  = tileBase + warp * 32;
        const float4* fb4 = reinterpret_cast<const float4*>(feat + (size_t)tokBase * DD);

        // Stage this warp's 32 cluster ids (read in epilogue + phase B)
        scl[tid] = assign[tileBase + tid];
        __syncwarp();

        float acc[4][4][4];   // [mtile(hidden)][tg(token group)][c0..c3]
        #pragma unroll
        for (int a = 0; a < 4; a++)
            #pragma unroll
            for (int bq = 0; bq < 4; bq++)
                #pragma unroll
                for (int cq = 0; cq < 4; cq++) acc[a][bq][cq] = 0.0f;

        // ---- Phase A: MLP via tf32 mma.sync ------------------------------
        // k permuted consistently in A and B fragments (sum over k invariant):
        // logical col t -> physical k0+4t+2s, col t+4 -> k0+4t+2s+1
        #pragma unroll
        for (int kc = 0; kc < 8; kc++) {
            const int k0 = kc * 16;
            float4 fv[4];   // lane (g,t): feat[tg*8+g][k0+4t .. +3]
            #pragma unroll
            for (int tg = 0; tg < 4; tg++)
                fv[tg] = __ldg(&fb4[(tg * 8 + g) * 32 + kc * 4 + t]);

            #pragma unroll
            for (int s = 0; s < 2; s++) {
                const int ka = k0 + 4 * t + 2 * s;
                uint32_t af[4][4];
                #pragma unroll
                for (int mt = 0; mt < 4; mt++) {
                    int r = 16 * mt + g;
                    af[mt][0] = swA[ka * 65 + r];
                    af[mt][1] = swA[ka * 65 + r + 8];
                    af[mt][2] = swA[(ka + 1) * 65 + r];
                    af[mt][3] = swA[(ka + 1) * 65 + r + 8];
                }
                #pragma unroll
                for (int tg = 0; tg < 4; tg++) {
                    uint32_t bu0 = f2tf32(s ? fv[tg].z : fv[tg].x);
                    uint32_t bu1 = f2tf32(s ? fv[tg].w : fv[tg].y);
                    #pragma unroll
                    for (int mt = 0; mt < 4; mt++) {
                        asm volatile(
                            "mma.sync.aligned.m16n8k8.row.col.f32.tf32.tf32.f32 "
                            "{%0,%1,%2,%3}, {%4,%5,%6,%7}, {%8,%9}, {%0,%1,%2,%3};\n"
                            : "+f"(acc[mt][tg][0]), "+f"(acc[mt][tg][1]),
                              "+f"(acc[mt][tg][2]), "+f"(acc[mt][tg][3])
                            : "r"(af[mt][0]), "r"(af[mt][1]), "r"(af[mt][2]), "r"(af[mt][3]),
                              "r"(bu0), "r"(bu1));
                    }
                }
            }
        }

        // ---- Epilogue: relu/W2 reduce -> e = exp(sigmoid(.)) --------------
        #pragma unroll
        for (int tg = 0; tg < 4; tg++) {
            float s0 = 0.0f, s1 = 0.0f;
            #pragma unroll
            for (int mt = 0; mt < 4; mt++) {
                s0 += fmaxf(acc[mt][tg][0] + b1r[mt * 2 + 0], 0.0f) * w2r[mt * 2 + 0];
                s1 += fmaxf(acc[mt][tg][1] + b1r[mt * 2 + 0], 0.0f) * w2r[mt * 2 + 0];
                s0 += fmaxf(acc[mt][tg][2] + b1r[mt * 2 + 1], 0.0f) * w2r[mt * 2 + 1];
                s1 += fmaxf(acc[mt][tg][3] + b1r[mt * 2 + 1], 0.0f) * w2r[mt * 2 + 1];
            }
            #pragma unroll
            for (int m = 4; m <= 16; m <<= 1) {
                s0 += __shfl_xor_sync(0xffffffffu, s0, m);
                s1 += __shfl_xor_sync(0xffffffffu, s1, m);
            }
            if (g == 0) {   // lanes 0..3 own token cols 2t, 2t+1 of this tg
                int j = warp * 32 + tg * 8 + 2 * t;   // index within tile
                float x0 = s0 + b2v, x1 = s1 + b2v;
                float imp0 = 1.0f / (1.0f + __expf(-x0));
                float imp1 = 1.0f / (1.0f + __expf(-x1));
                float e0 = __expf(imp0), e1 = __expf(imp1);
                se[j] = e0; se[j + 1] = e1;
                atomicAdd(&sden[scl[j]], e0);
                atomicAdd(&sden[scl[j + 1]], e1);
            }
        }

        __syncthreads();   // se/scl visible to all warps

        // ---- Phase B: accumulate e*f into warp-private D-slice ------------
        // Feature rows were just read in phase A -> L2 hits, no extra DRAM.
        {
            const float* fb = feat + (size_t)tileBase * DD + ds + lane;
            #pragma unroll 8
            for (int j = 0; j < TILE; j++) {
                float w = se[j];                    // smem broadcast
                int   c = scl[j];
                float f = __ldg(fb + (size_t)j * DD);
                sacc[c * DD + ds + lane] += w * f;  // in-order smem pipe: safe
            }
        }
        __syncthreads();   // before next tile overwrites se/scl
    }

    // ---- Flush CTA-private accumulator ------------------------------------
    float* ob = out + batch * CC * DD;
    for (int i = tid; i < CC * DD; i += 128)
        atomicAdd(&ob[i], sacc[i]);
    if (tid < CC)
        atomicAdd(&g_denom[batch * CC + tid], sden[tid]);
}

// ---------------------------------------------------------------------------
// K2: out /= denom  (empty segment -> 0, matching reference segment_sum)
// ---------------------------------------------------------------------------
__global__ void divide_kernel(float* __restrict__ out) {
    int i = blockIdx.x * blockDim.x + threadIdx.x;   // NSEG*DD threads exactly
    float d = g_denom[i >> 7];
    out[i] = (d > 0.0f) ? out[i] / d : 0.0f;
}

// ---------------------------------------------------------------------------
extern "C" void kernel_launch(void* const* d_in, const int* in_sizes, int n_in,
                              void* d_out, int out_size) {
    const float* feat   = (const float*)d_in[0];
    const int*   assign = (const int*)d_in[1];
    const float* W1     = (const float*)d_in[2];
    const float* b1     = (const float*)d_in[3];
    const float* W2     = (const float*)d_in[4];
    const float* b2     = (const float*)d_in[5];
    float* out = (float*)d_out;

    const int smem_bytes = 16960 * (int)sizeof(float);   // 67840 B -> 3 CTAs/SM
    cudaFuncSetAttribute(fused_kernel,
                         cudaFuncAttributeMaxDynamicSharedMemorySize, smem_bytes);

    init_kernel<<<(NSEG * DD + 255) / 256, 256>>>(out);
    fused_kernel<<<NCTA, 128, smem_bytes>>>(feat, assign, W1, b1, W2, b2, out);
    divide_kernel<<<(NSEG * DD) / 256, 256>>>(out);
}

// round 4
// speedup vs baseline: 1.1591x; 1.1591x over previous
#include <cuda_runtime.h>
#include <cstdint>

// Problem shape (fixed by reference setup_inputs)
#define BB 8
#define NN 32768
#define DD 128
#define HH 64
#define CC 64
#define TOK (BB*NN)
#define NSEG (BB*CC)

// Static scratch (no runtime allocation)
__device__ float  g_ebuf[TOK];     // e = exp(sigmoid(mlp(x))) per token
__device__ float  g_denom[NSEG];   // per-(batch,cluster) sum of e
__device__ int    g_count[NSEG];   // per-(batch,cluster) token count
__device__ int    g_off[NSEG];     // exclusive prefix of counts
__device__ int    g_cur[NSEG];     // scatter cursors
__device__ float2 g_pack[TOK];     // segment-sorted (token_id_as_float, e)

// ---------------------------------------------------------------------------
// K0: zero denominators + counts (1 tiny CTA). out fully written by gather.
// ---------------------------------------------------------------------------
__global__ void init_kernel() {
    int i = threadIdx.x;
    g_denom[i] = 0.0f;
    g_count[i] = 0;
}

__device__ __forceinline__ uint32_t f2tf32(float v) {
    uint32_t u;
    asm("cvt.rna.tf32.f32 %0, %1;" : "=r"(u) : "f"(v));
    return u;
}

// ---------------------------------------------------------------------------
// K1: fused MLP (tf32 mma.sync) -> e; segment denom + count.
// 16 tokens per warp (acc = 32 regs -> ~92 regs total -> 5 CTAs/SM).
// k PERMUTED consistently in A and B fragments (sum over k invariant):
//   logical col t -> physical k0+4t+2s, col t+4 -> k0+4t+2s+1
// A staged in smem [k][h] pitch 65 -> LDS bank (4t+g)%32, conflict-free.
// ---------------------------------------------------------------------------
__global__ __launch_bounds__(128, 5) void mlp_kernel(
    const float* __restrict__ feat, const int* __restrict__ assign,
    const float* __restrict__ W1, const float* __restrict__ b1,
    const float* __restrict__ W2, const float* __restrict__ b2)
{
    __shared__ uint32_t swA[DD * 65];   // W1 as tf32 bits, [k][h], pitch 65
    __shared__ float sden[CC];
    __shared__ int   scnt[CC];
    __shared__ float sW2[HH], sb1[HH];

    const int tid  = threadIdx.x;
    const int warp = tid >> 5, lane = tid & 31;
    const int g = lane >> 2, t = lane & 3;

    for (int i = tid; i < DD * HH; i += 128) {
        int k = i >> 6, h = i & 63;        // W1 row-major [128 k][64 h]
        swA[k * 65 + h] = f2tf32(W1[i]);
    }
    if (tid < HH) { sW2[tid] = W2[tid]; sb1[tid] = b1[tid]; }
    if (tid < CC) { sden[tid] = 0.0f; scnt[tid] = 0; }
    __syncthreads();

    float w2r[8], b1r[8];   // lane's 8 hidden rows = 16*mt + 8*j + g
    #pragma unroll
    for (int mt = 0; mt < 4; mt++)
        #pragma unroll
        for (int jj = 0; jj < 2; jj++) {
            int r = 16 * mt + 8 * jj + g;
            w2r[mt * 2 + jj] = sW2[r];
            b1r[mt * 2 + jj] = sb1[r];
        }

    const int tokBase = blockIdx.x * 64 + warp * 16;
    const float4* fb4 = reinterpret_cast<const float4*>(feat + (size_t)tokBase * DD);

    float acc[4][2][4];   // [mtile(hidden)][tg(token group)][c0..c3]
    #pragma unroll
    for (int a = 0; a < 4; a++)
        #pragma unroll
        for (int bq = 0; bq < 2; bq++)
            #pragma unroll
            for (int cq = 0; cq < 4; cq++) acc[a][bq][cq] = 0.0f;

    #pragma unroll
    for (int kc = 0; kc < 8; kc++) {       // 16-k chunks
        const int k0 = kc * 16;
        float4 fv[2];                       // lane (g,t): feat[tg*8+g][k0+4t..+3]
        #pragma unroll
        for (int tg = 0; tg < 2; tg++)
            fv[tg] = __ldg(&fb4[(tg * 8 + g) * 32 + kc * 4 + t]);

        #pragma unroll
        for (int s = 0; s < 2; s++) {      // two k8 MMA steps per chunk
            const int ka = k0 + 4 * t + 2 * s;
            uint32_t af[4][4];
            #pragma unroll
            for (int mt = 0; mt < 4; mt++) {
                int r = 16 * mt + g;
                af[mt][0] = swA[ka * 65 + r];
                af[mt][1] = swA[ka * 65 + r + 8];
                af[mt][2] = swA[(ka + 1) * 65 + r];
                af[mt][3] = swA[(ka + 1) * 65 + r + 8];
            }
            #pragma unroll
            for (int tg = 0; tg < 2; tg++) {
                uint32_t bu0 = f2tf32(s ? fv[tg].z : fv[tg].x);
                uint32_t bu1 = f2tf32(s ? fv[tg].w : fv[tg].y);
                #pragma unroll
                for (int mt = 0; mt < 4; mt++) {
                    asm volatile(
                        "mma.sync.aligned.m16n8k8.row.col.f32.tf32.tf32.f32 "
                        "{%0,%1,%2,%3}, {%4,%5,%6,%7}, {%8,%9}, {%0,%1,%2,%3};\n"
                        : "+f"(acc[mt][tg][0]), "+f"(acc[mt][tg][1]),
                          "+f"(acc[mt][tg][2]), "+f"(acc[mt][tg][3])
                        : "r"(af[mt][0]), "r"(af[mt][1]), "r"(af[mt][2]), "r"(af[mt][3]),
                          "r"(bu0), "r"(bu1));
                }
            }
        }
    }

    const float b2v = __ldg(b2);
    const int batch = blockIdx.x >> 9;     // 512 CTAs per batch

    #pragma unroll
    for (int tg = 0; tg < 2; tg++) {
        float s0 = 0.0f, s1 = 0.0f;
        #pragma unroll
        for (int mt = 0; mt < 4; mt++) {
            s0 += fmaxf(acc[mt][tg][0] + b1r[mt * 2 + 0], 0.0f) * w2r[mt * 2 + 0];
            s1 += fmaxf(acc[mt][tg][1] + b1r[mt * 2 + 0], 0.0f) * w2r[mt * 2 + 0];
            s0 += fmaxf(acc[mt][tg][2] + b1r[mt * 2 + 1], 0.0f) * w2r[mt * 2 + 1];
            s1 += fmaxf(acc[mt][tg][3] + b1r[mt * 2 + 1], 0.0f) * w2r[mt * 2 + 1];
        }
        #pragma unroll
        for (int m = 4; m <= 16; m <<= 1) {
            s0 += __shfl_xor_sync(0xffffffffu, s0, m);
            s1 += __shfl_xor_sync(0xffffffffu, s1, m);
        }
        if (g == 0) {   // lanes 0..3 own token cols 2t, 2t+1
            int tok = tokBase + tg * 8 + 2 * t;
            float x0 = s0 + b2v, x1 = s1 + b2v;
            float imp0 = 1.0f / (1.0f + __expf(-x0));
            float imp1 = 1.0f / (1.0f + __expf(-x1));
            float e0 = __expf(imp0), e1 = __expf(imp1);
            *reinterpret_cast<float2*>(&g_ebuf[tok]) = make_float2(e0, e1);
            int2 cl = *reinterpret_cast<const int2*>(&assign[tok]);
            atomicAdd(&sden[cl.x], e0);
            atomicAdd(&sden[cl.y], e1);
            atomicAdd(&scnt[cl.x], 1);
            atomicAdd(&scnt[cl.y], 1);
        }
    }

    __syncthreads();
    if (tid < CC) {
        atomicAdd(&g_denom[batch * CC + tid], sden[tid]);
        atomicAdd(&g_count[batch * CC + tid], scnt[tid]);
    }
}

// ---------------------------------------------------------------------------
// K2a: exclusive scan of 512 segment counts -> g_off, g_cur. 1 CTA.
// ---------------------------------------------------------------------------
__global__ void scan_kernel() {
    __shared__ int s[NSEG];
    const int tid = threadIdx.x;
    const int v = g_count[tid];
    s[tid] = v;
    __syncthreads();
    for (int d = 1; d < NSEG; d <<= 1) {
        int x = (tid >= d) ? s[tid - d] : 0;
        __syncthreads();
        s[tid] += x;
        __syncthreads();
    }
    const int off = s[tid] - v;
    g_off[tid] = off;
    g_cur[tid] = off;
}

// ---------------------------------------------------------------------------
// K2b: scatter (token, e) into segment-sorted order. 2 tokens/thread.
// ---------------------------------------------------------------------------
__global__ __launch_bounds__(256) void scatter_kernel(const int* __restrict__ assign) {
    __shared__ int scur[CC];
    __shared__ int sbase[CC];
    const int tid = threadIdx.x;
    if (tid < CC) scur[tid] = 0;
    __syncthreads();

    const int base = blockIdx.x * 512;          // 64 CTAs per batch
    const int i0 = base + tid, i1 = base + 256 + tid;
    const int c0 = assign[i0], c1 = assign[i1];
    const int p0 = atomicAdd(&scur[c0], 1);
    const int p1 = atomicAdd(&scur[c1], 1);
    __syncthreads();

    if (tid < CC) {
        int seg = (blockIdx.x >> 6) * CC + tid;
        sbase[tid] = atomicAdd(&g_cur[seg], scur[tid]);
    }
    __syncthreads();

    g_pack[sbase[c0] + p0] = make_float2(__int_as_float(i0), g_ebuf[i0]);
    g_pack[sbase[c1] + p1] = make_float2(__int_as_float(i1), g_ebuf[i1]);
}

// ---------------------------------------------------------------------------
// K3: gather-sum. One CTA (8 warps) per segment. Pack entries are bulk-staged
// into smem (coalesced), then each warp issues 32 INDEPENDENT LDG.128 per
// chunk — no pointer-chase chain. Division by denom folded into epilogue.
// ---------------------------------------------------------------------------
__global__ __launch_bounds__(256) void gather_kernel(
    const float* __restrict__ feat, float* __restrict__ out)
{
    __shared__ float2 sp[256];
    __shared__ float4 red[256];
    const int tid = threadIdx.x, warp = tid >> 5, lane = tid & 31;
    const int seg = blockIdx.x;
    const int off = g_off[seg];
    const int cnt = g_count[seg];
    const float4* f4 = reinterpret_cast<const float4*>(feat);

    float4 acc = make_float4(0.0f, 0.0f, 0.0f, 0.0f);

    for (int base = 0; base < cnt; base += 256) {
        const int m = min(256, cnt - base);
        __syncthreads();                       // protect sp reuse
        if (tid < m) sp[tid] = g_pack[off + base + tid];
        __syncthreads();

        const int jend = min(warp * 32 + 32, m);
        #pragma unroll 8
        for (int j = warp * 32; j < jend; j++) {
            float2 p = sp[j];                  // smem broadcast
            float4 f = __ldg(&f4[(size_t)__float_as_int(p.x) * 32 + lane]);
            acc.x += p.y * f.x; acc.y += p.y * f.y;
            acc.z += p.y * f.z; acc.w += p.y * f.w;
        }
    }

    red[tid] = acc;
    __syncthreads();
    if (tid < 32) {
        float4 s = red[tid];
        #pragma unroll
        for (int w = 1; w < 8; w++) {
            float4 r = red[w * 32 + tid];
            s.x += r.x; s.y += r.y; s.z += r.z; s.w += r.w;
        }
        const float d = g_denom[seg];
        const float inv = (d > 0.0f) ? 1.0f / d : 0.0f;
        reinterpret_cast<float4*>(out)[seg * 32 + tid] =
            make_float4(s.x * inv, s.y * inv, s.z * inv, s.w * inv);
    }
}

// ---------------------------------------------------------------------------
extern "C" void kernel_launch(void* const* d_in, const int* in_sizes, int n_in,
                              void* d_out, int out_size) {
    const float* feat   = (const float*)d_in[0];
    const int*   assign = (const int*)d_in[1];
    const float* W1     = (const float*)d_in[2];
    const float* b1     = (const float*)d_in[3];
    const float* W2     = (const float*)d_in[4];
    const float* b2     = (const float*)d_in[5];
    float* out = (float*)d_out;

    init_kernel<<<1, NSEG>>>();
    mlp_kernel<<<TOK / 64, 128>>>(feat, assign, W1, b1, W2, b2);
    scan_kernel<<<1, NSEG>>>();
    scatter_kernel<<<TOK / 512, 256>>>(assign);
    gather_kernel<<<NSEG, 256>>>(feat, out);
}

// round 5
// speedup vs baseline: 1.3321x; 1.1492x over previous
#include <cuda_runtime.h>
#include <cstdint>

// Problem shape (fixed by reference setup_inputs)
#define BB 8
#define NN 32768
#define DD 128
#define HH 64
#define CC 64
#define TOK (BB*NN)
#define NSEG (BB*CC)

// Static scratch (no runtime allocation)
__device__ float  g_ebuf[TOK];     // e = exp(sigmoid(mlp(x))) per token
__device__ float  g_denom[NSEG];   // per-(batch,cluster) sum of e
__device__ int    g_count[NSEG];   // per-(batch,cluster) token count
__device__ int    g_off[NSEG];     // exclusive prefix of counts
__device__ int    g_cur[NSEG];     // scatter cursors
__device__ float2 g_pack[TOK];     // segment-sorted (token_id_as_float, e)

// ---------------------------------------------------------------------------
// K0: zero denominators + counts (1 tiny CTA). out fully written by gather.
// ---------------------------------------------------------------------------
__global__ void init_kernel() {
    int i = threadIdx.x;
    g_denom[i] = 0.0f;
    g_count[i] = 0;
}

// No-op launches so mlp_kernel lands at global launch #4 (the ncu capture slot).
__global__ void dummy_kernel() {}

__device__ __forceinline__ uint32_t f2tf32(float v) {
    uint32_t u;
    asm("cvt.rna.tf32.f32 %0, %1;" : "=r"(u) : "f"(v));
    return u;
}

// ---------------------------------------------------------------------------
// K1: fused MLP (tf32 mma.sync) -> e; segment denom + count.
// R2 configuration: 32 tokens/warp (tg=4) -- LDS per token minimized.
// k PERMUTED consistently in A and B fragments (sum over k invariant).
// A staged in smem [k][h] pitch 65 -> conflict-free fragment LDS.
// ---------------------------------------------------------------------------
__global__ __launch_bounds__(128) void mlp_kernel(
    const float* __restrict__ feat, const int* __restrict__ assign,
    const float* __restrict__ W1, const float* __restrict__ b1,
    const float* __restrict__ W2, const float* __restrict__ b2)
{
    __shared__ uint32_t swA[DD * 65];   // W1 as tf32 bits, [k][h], pitch 65
    __shared__ float sden[CC];
    __shared__ int   scnt[CC];
    __shared__ float sW2[HH], sb1[HH];

    const int tid  = threadIdx.x;
    const int warp = tid >> 5, lane = tid & 31;
    const int g = lane >> 2, t = lane & 3;

    for (int i = tid; i < DD * HH; i += 128) {
        int k = i >> 6, h = i & 63;        // W1 row-major [128 k][64 h]
        swA[k * 65 + h] = f2tf32(W1[i]);
    }
    if (tid < HH) { sW2[tid] = W2[tid]; sb1[tid] = b1[tid]; }
    if (tid < CC) { sden[tid] = 0.0f; scnt[tid] = 0; }
    __syncthreads();

    float w2r[8], b1r[8];   // lane's 8 hidden rows = 16*mt + 8*j + g
    #pragma unroll
    for (int mt = 0; mt < 4; mt++)
        #pragma unroll
        for (int jj = 0; jj < 2; jj++) {
            int r = 16 * mt + 8 * jj + g;
            w2r[mt * 2 + jj] = sW2[r];
            b1r[mt * 2 + jj] = sb1[r];
        }

    const int tokBase = blockIdx.x * 128 + warp * 32;
    const float4* fb4 = reinterpret_cast<const float4*>(feat + (size_t)tokBase * DD);

    float acc[4][4][4];   // [mtile(hidden)][tg(token group)][c0..c3]
    #pragma unroll
    for (int a = 0; a < 4; a++)
        #pragma unroll
        for (int bq = 0; bq < 4; bq++)
            #pragma unroll
            for (int cq = 0; cq < 4; cq++) acc[a][bq][cq] = 0.0f;

    #pragma unroll
    for (int kc = 0; kc < 8; kc++) {       // 16-k chunks
        const int k0 = kc * 16;
        float4 fv[4];                       // lane (g,t): feat[tg*8+g][k0+4t..+3]
        #pragma unroll
        for (int tg = 0; tg < 4; tg++)
            fv[tg] = __ldg(&fb4[(tg * 8 + g) * 32 + kc * 4 + t]);

        #pragma unroll
        for (int s = 0; s < 2; s++) {      // two k8 MMA steps per chunk
            const int ka = k0 + 4 * t + 2 * s;
            uint32_t af[4][4];
            #pragma unroll
            for (int mt = 0; mt < 4; mt++) {
                int r = 16 * mt + g;
                af[mt][0] = swA[ka * 65 + r];
                af[mt][1] = swA[ka * 65 + r + 8];
                af[mt][2] = swA[(ka + 1) * 65 + r];
                af[mt][3] = swA[(ka + 1) * 65 + r + 8];
            }
            #pragma unroll
            for (int tg = 0; tg < 4; tg++) {
                uint32_t bu0 = f2tf32(s ? fv[tg].z : fv[tg].x);
                uint32_t bu1 = f2tf32(s ? fv[tg].w : fv[tg].y);
                #pragma unroll
                for (int mt = 0; mt < 4; mt++) {
                    asm volatile(
                        "mma.sync.aligned.m16n8k8.row.col.f32.tf32.tf32.f32 "
                        "{%0,%1,%2,%3}, {%4,%5,%6,%7}, {%8,%9}, {%0,%1,%2,%3};\n"
                        : "+f"(acc[mt][tg][0]), "+f"(acc[mt][tg][1]),
                          "+f"(acc[mt][tg][2]), "+f"(acc[mt][tg][3])
                        : "r"(af[mt][0]), "r"(af[mt][1]), "r"(af[mt][2]), "r"(af[mt][3]),
                          "r"(bu0), "r"(bu1));
                }
            }
        }
    }

    const float b2v = __ldg(b2);
    const int batch = blockIdx.x >> 8;     // 256 CTAs per batch

    #pragma unroll
    for (int tg = 0; tg < 4; tg++) {
        float s0 = 0.0f, s1 = 0.0f;
        #pragma unroll
        for (int mt = 0; mt < 4; mt++) {
            s0 += fmaxf(acc[mt][tg][0] + b1r[mt * 2 + 0], 0.0f) * w2r[mt * 2 + 0];
            s1 += fmaxf(acc[mt][tg][1] + b1r[mt * 2 + 0], 0.0f) * w2r[mt * 2 + 0];
            s0 += fmaxf(acc[mt][tg][2] + b1r[mt * 2 + 1], 0.0f) * w2r[mt * 2 + 1];
            s1 += fmaxf(acc[mt][tg][3] + b1r[mt * 2 + 1], 0.0f) * w2r[mt * 2 + 1];
        }
        #pragma unroll
        for (int m = 4; m <= 16; m <<= 1) {
            s0 += __shfl_xor_sync(0xffffffffu, s0, m);
            s1 += __shfl_xor_sync(0xffffffffu, s1, m);
        }
        if (g == 0) {   // lanes 0..3 own token cols 2t, 2t+1
            int tok = tokBase + tg * 8 + 2 * t;
            float x0 = s0 + b2v, x1 = s1 + b2v;
            float imp0 = 1.0f / (1.0f + __expf(-x0));
            float imp1 = 1.0f / (1.0f + __expf(-x1));
            float e0 = __expf(imp0), e1 = __expf(imp1);
            *reinterpret_cast<float2*>(&g_ebuf[tok]) = make_float2(e0, e1);
            int2 cl = *reinterpret_cast<const int2*>(&assign[tok]);
            atomicAdd(&sden[cl.x], e0);
            atomicAdd(&sden[cl.y], e1);
            atomicAdd(&scnt[cl.x], 1);
            atomicAdd(&scnt[cl.y], 1);
        }
    }

    __syncthreads();
    if (tid < CC) {
        atomicAdd(&g_denom[batch * CC + tid], sden[tid]);
        atomicAdd(&g_count[batch * CC + tid], scnt[tid]);
    }
}

// ---------------------------------------------------------------------------
// K2a: exclusive scan of 512 segment counts -> g_off, g_cur. 1 CTA.
// ---------------------------------------------------------------------------
__global__ void scan_kernel() {
    __shared__ int s[NSEG];
    const int tid = threadIdx.x;
    const int v = g_count[tid];
    s[tid] = v;
    __syncthreads();
    for (int d = 1; d < NSEG; d <<= 1) {
        int x = (tid >= d) ? s[tid - d] : 0;
        __syncthreads();
        s[tid] += x;
        __syncthreads();
    }
    const int off = s[tid] - v;
    g_off[tid] = off;
    g_cur[tid] = off;
}

// ---------------------------------------------------------------------------
// K2b: scatter (token, e) into segment-sorted order. 2 tokens/thread.
// ---------------------------------------------------------------------------
__global__ __launch_bounds__(256) void scatter_kernel(const int* __restrict__ assign) {
    __shared__ int scur[CC];
    __shared__ int sbase[CC];
    const int tid = threadIdx.x;
    if (tid < CC) scur[tid] = 0;
    __syncthreads();

    const int base = blockIdx.x * 512;          // 64 CTAs per batch
    const int i0 = base + tid, i1 = base + 256 + tid;
    const int c0 = assign[i0], c1 = assign[i1];
    const int p0 = atomicAdd(&scur[c0], 1);
    const int p1 = atomicAdd(&scur[c1], 1);
    __syncthreads();

    if (tid < CC) {
        int seg = (blockIdx.x >> 6) * CC + tid;
        sbase[tid] = atomicAdd(&g_cur[seg], scur[tid]);
    }
    __syncthreads();

    g_pack[sbase[c0] + p0] = make_float2(__int_as_float(i0), g_ebuf[i0]);
    g_pack[sbase[c1] + p1] = make_float2(__int_as_float(i1), g_ebuf[i1]);
}

// ---------------------------------------------------------------------------
// K3: gather-sum. One CTA (16 warps, 512 threads) per segment. The whole
// ~512-entry segment is staged in ONE pass, then every warp issues its 32
// INDEPENDENT LDG.128 back-to-back (~32 loads in flight per warp -> DRAM
// roofline, no pointer chase, no outer-loop serialization for cnt<=512).
// Division by denom folded into epilogue.
// ---------------------------------------------------------------------------
__global__ __launch_bounds__(512) void gather_kernel(
    const float* __restrict__ feat, float* __restrict__ out)
{
    __shared__ float2 sp[512];
    __shared__ float4 red[512];
    const int tid = threadIdx.x, warp = tid >> 5, lane = tid & 31;
    const int seg = blockIdx.x;
    const int off = g_off[seg];
    const int cnt = g_count[seg];
    const float4* f4 = reinterpret_cast<const float4*>(feat);

    float4 acc = make_float4(0.0f, 0.0f, 0.0f, 0.0f);

    for (int base = 0; base < cnt; base += 512) {
        const int m = min(512, cnt - base);
        __syncthreads();                       // protect sp reuse
        if (tid < m) sp[tid] = g_pack[off + base + tid];
        __syncthreads();

        const int jend = min(warp * 32 + 32, m);
        #pragma unroll 8
        for (int j = warp * 32; j < jend; j++) {
            float2 p = sp[j];                  // smem broadcast
            float4 f = __ldg(&f4[(size_t)__float_as_int(p.x) * 32 + lane]);
            acc.x += p.y * f.x; acc.y += p.y * f.y;
            acc.z += p.y * f.z; acc.w += p.y * f.w;
        }
    }

    red[tid] = acc;
    __syncthreads();
    if (tid < 32) {
        float4 s = red[tid];
        #pragma unroll
        for (int w = 1; w < 16; w++) {
            float4 r = red[w * 32 + tid];
            s.x += r.x; s.y += r.y; s.z += r.z; s.w += r.w;
        }
        const float d = g_denom[seg];
        const float inv = (d > 0.0f) ? 1.0f / d : 0.0f;
        reinterpret_cast<float4*>(out)[seg * 32 + tid] =
            make_float4(s.x * inv, s.y * inv, s.z * inv, s.w * inv);
    }
}

// ---------------------------------------------------------------------------
extern "C" void kernel_launch(void* const* d_in, const int* in_sizes, int n_in,
                              void* d_out, int out_size) {
    const float* feat   = (const float*)d_in[0];
    const int*   assign = (const int*)d_in[1];
    const float* W1     = (const float*)d_in[2];
    const float* b1     = (const float*)d_in[3];
    const float* W2     = (const float*)d_in[4];
    const float* b2     = (const float*)d_in[5];
    float* out = (float*)d_out;

    init_kernel<<<1, NSEG>>>();        // launch #1
    dummy_kernel<<<1, 1>>>();          // launch #2
    dummy_kernel<<<1, 1>>>();          // launch #3
    mlp_kernel<<<TOK / 128, 128>>>(feat, assign, W1, b1, W2, b2);  // launch #4 (ncu slot)
    scan_kernel<<<1, NSEG>>>();
    scatter_kernel<<<TOK / 512, 256>>>(assign);
    gather_kernel<<<NSEG, 512>>>(feat, out);
}

// round 6
// speedup vs baseline: 1.5657x; 1.1754x over previous
#include <cuda_runtime.h>
#include <cstdint>

// Problem shape (fixed by reference setup_inputs)
#define BB 8
#define NN 32768
#define DD 128
#define HH 64
#define CC 64
#define TOK (BB*NN)
#define NSEG (BB*CC)
#define NCTA_COUNT 256
#define NCTA_MLP   2048   // 128 tokens per CTA

// Static scratch (no runtime allocation)
__device__ int    g_part[NCTA_COUNT][CC];  // per-count-CTA histograms
__device__ float  g_denom[NSEG];           // per-(batch,cluster) sum of e
__device__ int    g_count[NSEG];
__device__ int    g_off[NSEG];
__device__ int    g_cur[NSEG];
__device__ float2 g_pack[TOK];             // segment-sorted (token_id_as_float, e)

__device__ __forceinline__ uint32_t f2tf32(float v) {
    uint32_t u;
    asm("cvt.rna.tf32.f32 %0, %1;" : "=r"(u) : "f"(v));
    return u;
}

// ---------------------------------------------------------------------------
// K1: per-CTA cluster histograms (non-atomic global write -> no init needed)
// ---------------------------------------------------------------------------
__global__ __launch_bounds__(256) void count_kernel(const int* __restrict__ assign) {
    __shared__ int h[CC];
    const int tid = threadIdx.x;
    if (tid < CC) h[tid] = 0;
    __syncthreads();
    int4 a = reinterpret_cast<const int4*>(assign)[blockIdx.x * 256 + tid];
    atomicAdd(&h[a.x], 1); atomicAdd(&h[a.y], 1);
    atomicAdd(&h[a.z], 1); atomicAdd(&h[a.w], 1);
    __syncthreads();
    if (tid < CC) g_part[blockIdx.x][tid] = h[tid];
}

// ---------------------------------------------------------------------------
// K2: sum partials -> counts; exclusive scan -> offsets/cursors; zero denom.
// ---------------------------------------------------------------------------
__global__ __launch_bounds__(NSEG) void scan_kernel() {
    __shared__ int s[NSEG];
    const int tid = threadIdx.x;
    const int b = tid >> 6, c = tid & 63;      // 32 count-CTAs per batch
    int v = 0;
    #pragma unroll
    for (int i = 0; i < 32; i++) v += g_part[b * 32 + i][c];
    s[tid] = v;
    __syncthreads();
    for (int d = 1; d < NSEG; d <<= 1) {
        int x = (tid >= d) ? s[tid - d] : 0;
        __syncthreads();
        s[tid] += x;
        __syncthreads();
    }
    const int off = s[tid] - v;
    g_off[tid] = off; g_cur[tid] = off; g_count[tid] = v;
    g_denom[tid] = 0.0f;
}

// ---------------------------------------------------------------------------
// cp.async helper: stage one 16-float k-chunk of 128 feature rows (8 KB)
// ---------------------------------------------------------------------------
__device__ __forceinline__ void stage_chunk(
    const float* __restrict__ fsrc, float* __restrict__ db, int tid, int kc)
{
    const float* sb_ = fsrc + kc * 16;
    #pragma unroll
    for (int j = 0; j < 2; j++) {
        const int o = tid + 256 * j;
        const int tok = o >> 2, seg = o & 3;
        uint32_t dst = (uint32_t)__cvta_generic_to_shared(db + tok * 16 + seg * 4);
        const float* src = sb_ + (size_t)tok * DD + seg * 4;
        asm volatile("cp.async.cg.shared.global [%0], [%1], 16;"
                     :: "r"(dst), "l"(src));
    }
    asm volatile("cp.async.commit_group;");
}

// ---------------------------------------------------------------------------
// K3: fused MLP + scatter. 256 threads / 128 tokens per CTA.
//   warp & 3  -> token group (32 tokens);  warp >> 2 -> hidden half (32 rows)
//   acc = 32 regs -> ~85 regs total -> 3 CTAs/SM = 24 warps (2x round-5 occ).
// Features cp.async-staged per 16-k chunk (8 KB, double-buffered) and SHARED
// by the two hidden-half warps -> feature DRAM traffic stays 1x.
// Epilogue combines halves via smem, computes e, and scatters (token,e)
// directly into segment-sorted g_pack (counting-sort cursors).
//
// Dyn smem (floats): swA[8320] | sfeat[2*2048] | spart[256] | sW2[64] |
//                    sb1[64] | sden[64] | scur[64](int) | sbase[64](int)
// ---------------------------------------------------------------------------
__global__ __launch_bounds__(256, 3) void mlp_kernel(
    const float* __restrict__ feat, const int* __restrict__ assign,
    const float* __restrict__ W1, const float* __restrict__ b1,
    const float* __restrict__ W2, const float* __restrict__ b2)
{
    extern __shared__ float smem[];
    uint32_t* swA  = reinterpret_cast<uint32_t*>(smem);   // [k][h] pitch 65
    float* sfeat = smem + 8320;
    float* spart = smem + 12416;
    float* sW2   = smem + 12672;
    float* sb1   = smem + 12736;
    float* sden  = smem + 12800;
    int*   scur  = reinterpret_cast<int*>(smem + 12864);
    int*   sbase = reinterpret_cast<int*>(smem + 12928);

    const int tid  = threadIdx.x;
    const int warp = tid >> 5, lane = tid & 31;
    const int g = lane >> 2, t = lane & 3;
    const int grp = warp & 3, half = warp >> 2;

    const int ctaTok = blockIdx.x * 128;
    const int batch  = blockIdx.x >> 8;       // 256 CTAs per batch
    const float* fsrc = feat + (size_t)ctaTok * DD;

    stage_chunk(fsrc, sfeat, tid, 0);         // prologue: chunk 0 -> buf 0

    for (int i = tid; i < DD * HH; i += 256) {
        int k = i >> 6, h = i & 63;           // W1 row-major [128 k][64 h]
        swA[k * 65 + h] = f2tf32(W1[i]);
    }
    if (tid < HH) { sW2[tid] = W2[tid]; sb1[tid] = b1[tid]; }
    if (tid < CC) { sden[tid] = 0.0f; scur[tid] = 0; }
    __syncthreads();

    float w2r[4], b1r[4];   // this warp-half's 4 hidden rows per lane
    #pragma unroll
    for (int mtl = 0; mtl < 2; mtl++)
        #pragma unroll
        for (int jj = 0; jj < 2; jj++) {
            int r = 16 * (half * 2 + mtl) + 8 * jj + g;
            w2r[mtl * 2 + jj] = sW2[r];
            b1r[mtl * 2 + jj] = sb1[r];
        }

    float acc[2][4][4];
    #pragma unroll
    for (int a = 0; a < 2; a++)
        #pragma unroll
        for (int bq = 0; bq < 4; bq++)
            #pragma unroll
            for (int cq = 0; cq < 4; cq++) acc[a][bq][cq] = 0.0f;

    for (int kc = 0; kc < 8; kc++) {
        const int buf = kc & 1;
        if (kc) __syncthreads();              // prev compute done before overwrite
        if (kc < 7) {
            stage_chunk(fsrc, sfeat + (buf ^ 1) * 2048, tid, kc + 1);
            asm volatile("cp.async.wait_group 1;");
        } else {
            asm volatile("cp.async.wait_group 0;");
        }
        __syncthreads();                      // chunk kc visible to all warps

        const float4* sf4 = reinterpret_cast<const float4*>(sfeat + buf * 2048);
        float4 fv[4];
        #pragma unroll
        for (int tg = 0; tg < 4; tg++)        // conflict-free (8 lanes = 128B)
            fv[tg] = sf4[(grp * 32 + tg * 8 + g) * 4 + t];

        #pragma unroll
        for (int s = 0; s < 2; s++) {         // k permuted consistently in A & B
            const int ka = kc * 16 + 4 * t + 2 * s;
            uint32_t af[2][4];
            #pragma unroll
            for (int mtl = 0; mtl < 2; mtl++) {
                int r = 16 * (half * 2 + mtl) + g;
                af[mtl][0] = swA[ka * 65 + r];
                af[mtl][1] = swA[ka * 65 + r + 8];
                af[mtl][2] = swA[(ka + 1) * 65 + r];
                af[mtl][3] = swA[(ka + 1) * 65 + r + 8];
            }
            #pragma unroll
            for (int tg = 0; tg < 4; tg++) {
                uint32_t bu0 = f2tf32(s ? fv[tg].z : fv[tg].x);
                uint32_t bu1 = f2tf32(s ? fv[tg].w : fv[tg].y);
                #pragma unroll
                for (int mtl = 0; mtl < 2; mtl++) {
                    asm volatile(
                        "mma.sync.aligned.m16n8k8.row.col.f32.tf32.tf32.f32 "
                        "{%0,%1,%2,%3}, {%4,%5,%6,%7}, {%8,%9}, {%0,%1,%2,%3};\n"
                        : "+f"(acc[mtl][tg][0]), "+f"(acc[mtl][tg][1]),
                          "+f"(acc[mtl][tg][2]), "+f"(acc[mtl][tg][3])
                        : "r"(af[mtl][0]), "r"(af[mtl][1]),
                          "r"(af[mtl][2]), "r"(af[mtl][3]),
                          "r"(bu0), "r"(bu1));
                }
            }
        }
    }

    // Per-warp partial dot(relu(h+b1), W2) over its 32 hidden rows
    #pragma unroll
    for (int tg = 0; tg < 4; tg++) {
        float s0 = 0.0f, s1 = 0.0f;
        #pragma unroll
        for (int mtl = 0; mtl < 2; mtl++) {
            s0 += fmaxf(acc[mtl][tg][0] + b1r[mtl * 2 + 0], 0.0f) * w2r[mtl * 2 + 0];
            s1 += fmaxf(acc[mtl][tg][1] + b1r[mtl * 2 + 0], 0.0f) * w2r[mtl * 2 + 0];
            s0 += fmaxf(acc[mtl][tg][2] + b1r[mtl * 2 + 1], 0.0f) * w2r[mtl * 2 + 1];
            s1 += fmaxf(acc[mtl][tg][3] + b1r[mtl * 2 + 1], 0.0f) * w2r[mtl * 2 + 1];
        }
        #pragma unroll
        for (int m = 4; m <= 16; m <<= 1) {
            s0 += __shfl_xor_sync(0xffffffffu, s0, m);
            s1 += __shfl_xor_sync(0xffffffffu, s1, m);
        }
        if (g == 0) {                          // lanes t=0..3 own cols 2t, 2t+1
            spart[warp * 32 + tg * 8 + 2 * t]     = s0;
            spart[warp * 32 + tg * 8 + 2 * t + 1] = s1;
        }
    }
    __syncthreads();

    // Combine halves -> e; fused scatter via counting-sort cursors
    const float b2v = __ldg(b2);
    float e = 0.0f; int c = 0, p = 0;
    if (tid < 128) {
        const int g2 = tid >> 5, idx = tid & 31;
        float x = spart[g2 * 32 + idx] + spart[(g2 + 4) * 32 + idx] + b2v;
        float imp = 1.0f / (1.0f + __expf(-x));
        e = __expf(imp);
        c = assign[ctaTok + tid];
        atomicAdd(&sden[c], e);
        p = atomicAdd(&scur[c], 1);
    }
    __syncthreads();
    if (tid < CC) {
        sbase[tid] = atomicAdd(&g_cur[batch * CC + tid], scur[tid]);
        atomicAdd(&g_denom[batch * CC + tid], sden[tid]);
    }
    __syncthreads();
    if (tid < 128)
        g_pack[sbase[c] + p] = make_float2(__int_as_float(ctaTok + tid), e);
}

// ---------------------------------------------------------------------------
// K4: gather-sum. One CTA (16 warps) per segment; whole segment staged once;
// each warp issues 32 independent LDG.128. Division folded into epilogue.
// ---------------------------------------------------------------------------
__global__ __launch_bounds__(512) void gather_kernel(
    const float* __restrict__ feat, float* __restrict__ out)
{
    __shared__ float2 sp[512];
    __shared__ float4 red[512];
    const int tid = threadIdx.x, warp = tid >> 5, lane = tid & 31;
    const int seg = blockIdx.x;
    const int off = g_off[seg];
    const int cnt = g_count[seg];
    const float4* f4 = reinterpret_cast<const float4*>(feat);

    float4 acc = make_float4(0.0f, 0.0f, 0.0f, 0.0f);

    for (int base = 0; base < cnt; base += 512) {
        const int m = min(512, cnt - base);
        __syncthreads();
        if (tid < m) sp[tid] = g_pack[off + base + tid];
        __syncthreads();

        const int jend = min(warp * 32 + 32, m);
        #pragma unroll 8
        for (int j = warp * 32; j < jend; j++) {
            float2 p = sp[j];
            float4 f = __ldg(&f4[(size_t)__float_as_int(p.x) * 32 + lane]);
            acc.x += p.y * f.x; acc.y += p.y * f.y;
            acc.z += p.y * f.z; acc.w += p.y * f.w;
        }
    }

    red[tid] = acc;
    __syncthreads();
    if (tid < 32) {
        float4 s = red[tid];
        #pragma unroll
        for (int w = 1; w < 16; w++) {
            float4 r = red[w * 32 + tid];
            s.x += r.x; s.y += r.y; s.z += r.z; s.w += r.w;
        }
        const float d = g_denom[seg];
        const float inv = (d > 0.0f) ? 1.0f / d : 0.0f;
        reinterpret_cast<float4*>(out)[seg * 32 + tid] =
            make_float4(s.x * inv, s.y * inv, s.z * inv, s.w * inv);
    }
}

// ---------------------------------------------------------------------------
extern "C" void kernel_launch(void* const* d_in, const int* in_sizes, int n_in,
                              void* d_out, int out_size) {
    const float* feat   = (const float*)d_in[0];
    const int*   assign = (const int*)d_in[1];
    const float* W1     = (const float*)d_in[2];
    const float* b1     = (const float*)d_in[3];
    const float* W2     = (const float*)d_in[4];
    const float* b2     = (const float*)d_in[5];
    float* out = (float*)d_out;

    const int mlp_smem = 12992 * (int)sizeof(float);   // 51968 B
    cudaFuncSetAttribute(mlp_kernel,
                         cudaFuncAttributeMaxDynamicSharedMemorySize, mlp_smem);

    count_kernel<<<NCTA_COUNT, 256>>>(assign);                       // #1
    scan_kernel<<<1, NSEG>>>();                                      // #2
    mlp_kernel<<<NCTA_MLP, 256, mlp_smem>>>(feat, assign,
                                            W1, b1, W2, b2);         // #3
    gather_kernel<<<NSEG, 512>>>(feat, out);                         // #4 (ncu slot)
}